// round 3
// baseline (speedup 1.0000x reference)
#include <cuda_runtime.h>

#define Bn 8
#define Tn 1024
#define IND 512
#define NH 8
#define HD 64
#define OUTD 512
#define MAXPOS 512

// -------- scratch (allocations forbidden; device globals) --------
__device__ float g_q[(size_t)Bn*NH*Tn*HD];
__device__ float g_k[(size_t)Bn*NH*Tn*HD];
__device__ float g_v[(size_t)Bn*NH*Tn*HD];
__device__ float g_att[(size_t)Bn*Tn*OUTD];

__device__ __forceinline__ void mma8(float* c,
    unsigned a0, unsigned a1, unsigned a2, unsigned a3,
    unsigned b0, unsigned b1)
{
    asm volatile(
      "mma.sync.aligned.m16n8k8.row.col.f32.tf32.tf32.f32 "
      "{%0,%1,%2,%3},{%4,%5,%6,%7},{%8,%9},{%0,%1,%2,%3};"
      : "+f"(c[0]), "+f"(c[1]), "+f"(c[2]), "+f"(c[3])
      : "r"(a0), "r"(a1), "r"(a2), "r"(a3), "r"(b0), "r"(b1));
}

__device__ __forceinline__ void cpa16(unsigned dst, const void* src) {
    asm volatile("cp.async.ca.shared.global [%0], [%1], 16;" :: "r"(dst), "l"(src));
}
__device__ __forceinline__ void cpa_commit() {
    asm volatile("cp.async.commit_group;");
}

// ============================================================
// GEMM body shared by qkv/out: BM=128, BN=64, BK=16, 256 thr,
// double-buffered cp.async staging.  A row-major [*,lda], B row-major [k,ldb].
// ============================================================
#define GEMM_MAIN(APTR, LDA, BPTR, LDB)                                         \
    const int tid = threadIdx.x, lane = tid & 31, warp = tid >> 5;              \
    const int wr = warp >> 1, wc = warp & 1;                                    \
    const int lq = lane >> 2, lr = lane & 3;                                    \
    const int a_row = tid >> 2, a_kc = (tid & 3) << 2;                          \
    const int b_kr = tid >> 4, b_nc = (tid & 15) << 2;                          \
    unsigned sa_u = (unsigned)__cvta_generic_to_shared(s_a);                    \
    unsigned sb_u = (unsigned)__cvta_generic_to_shared(s_b);                    \
    float acc[2][4][4];                                                         \
    _Pragma("unroll") for (int i = 0; i < 2; i++)                               \
    _Pragma("unroll") for (int j = 0; j < 4; j++)                               \
    _Pragma("unroll") for (int e = 0; e < 4; e++) acc[i][j][e] = 0.f;           \
    /* prefetch k0 = 0 into buf 0 */                                            \
    {                                                                           \
        cpa16(sa_u + ((a_row*20 + a_kc))*4,                                     \
              (APTR) + (size_t)(row0 + a_row)*(LDA) + a_kc);                    \
        cpa16(sa_u + (((a_row+64)*20 + a_kc))*4,                                \
              (APTR) + (size_t)(row0 + a_row + 64)*(LDA) + a_kc);               \
        cpa16(sb_u + ((b_kr*68 + b_nc))*4,                                      \
              (BPTR) + (size_t)b_kr*(LDB) + b_nc);                              \
        cpa_commit();                                                           \
    }                                                                           \
    for (int it = 0; it < 32; it++) {                                           \
        const int buf = it & 1;                                                 \
        if (it < 31) {                                                          \
            const int kn = (it+1) << 4;                                         \
            const int bo = (buf^1) * (128*20) * 4;                              \
            const int bo2 = (buf^1) * (16*68) * 4;                              \
            cpa16(sa_u + bo + ((a_row*20 + a_kc))*4,                            \
                  (APTR) + (size_t)(row0 + a_row)*(LDA) + kn + a_kc);           \
            cpa16(sa_u + bo + (((a_row+64)*20 + a_kc))*4,                       \
                  (APTR) + (size_t)(row0 + a_row + 64)*(LDA) + kn + a_kc);      \
            cpa16(sb_u + bo2 + ((b_kr*68 + b_nc))*4,                            \
                  (BPTR) + (size_t)(kn + b_kr)*(LDB) + b_nc);                   \
            cpa_commit();                                                       \
            asm volatile("cp.async.wait_group 1;");                             \
        } else {                                                                \
            asm volatile("cp.async.wait_group 0;");                             \
        }                                                                       \
        __syncthreads();                                                        \
        const float* pa = s_a + buf*(128*20);                                   \
        const float* pb = s_b + buf*(16*68);                                    \
        _Pragma("unroll")                                                       \
        for (int ks = 0; ks < 2; ks++) {                                        \
            unsigned a[2][4], b[4][2];                                          \
            _Pragma("unroll")                                                   \
            for (int rt = 0; rt < 2; rt++) {                                    \
                int r = wr*32 + rt*16 + lq, k = ks*8 + lr;                      \
                a[rt][0] = __float_as_uint(pa[ r   *20 + k]);                   \
                a[rt][1] = __float_as_uint(pa[(r+8)*20 + k]);                   \
                a[rt][2] = __float_as_uint(pa[ r   *20 + k+4]);                 \
                a[rt][3] = __float_as_uint(pa[(r+8)*20 + k+4]);                 \
            }                                                                   \
            _Pragma("unroll")                                                   \
            for (int ct = 0; ct < 4; ct++) {                                    \
                int n = wc*32 + ct*8 + lq, k = ks*8 + lr;                       \
                b[ct][0] = __float_as_uint(pb[ k   *68 + n]);                   \
                b[ct][1] = __float_as_uint(pb[(k+4)*68 + n]);                   \
            }                                                                   \
            _Pragma("unroll")                                                   \
            for (int rt = 0; rt < 2; rt++)                                      \
            _Pragma("unroll")                                                   \
            for (int ct = 0; ct < 4; ct++)                                      \
                mma8(acc[rt][ct], a[rt][0],a[rt][1],a[rt][2],a[rt][3],          \
                     b[ct][0],b[ct][1]);                                        \
        }                                                                       \
        __syncthreads();                                                        \
    }

// ============================================================
// Kernel 1: QKV projection
// ============================================================
__global__ __launch_bounds__(256) void qkv_mma(
    const float* __restrict__ x,
    const float* __restrict__ Wq,  const float* __restrict__ bq,
    const float* __restrict__ Wkv, const float* __restrict__ bkv)
{
    __shared__ float s_a[2*128*20];
    __shared__ float s_b[2*16*68];

    const int row0 = blockIdx.y * 128, col0 = blockIdx.x * 64;
    const float* W; int ldw; const float* bias; int wcol;
    if (col0 < OUTD) { W = Wq;  ldw = OUTD;   wcol = col0;        bias = bq  + col0; }
    else             { W = Wkv; ldw = 2*OUTD; wcol = col0 - OUTD; bias = bkv + (col0 - OUTD); }
    const float* Bp = W + wcol;

    GEMM_MAIN(x, IND, Bp, ldw)

    const int seg = col0 >> 9;
    const int h   = (col0 & 511) >> 6;
    float* dst = (seg == 0) ? g_q : (seg == 1) ? g_k : g_v;

#pragma unroll
    for (int rt = 0; rt < 2; rt++)
#pragma unroll
        for (int ct = 0; ct < 4; ct++)
#pragma unroll
            for (int hh = 0; hh < 2; hh++) {
                int r  = row0 + wr*32 + rt*16 + lq + 8*hh;
                int bb = r >> 10, tt = r & 1023;
                int col = wc*32 + ct*8 + 2*lr;
                float2 w;
                w.x = acc[rt][ct][2*hh+0] + bias[col];
                w.y = acc[rt][ct][2*hh+1] + bias[col+1];
                *(float2*)(dst + ((size_t)(bb*NH + h)*Tn + tt)*HD + col) = w;
            }
}

// ============================================================
// Kernel 3: output projection
// ============================================================
__global__ __launch_bounds__(256) void out_mma(
    const float* __restrict__ Wout, const float* __restrict__ bout,
    float* __restrict__ out)
{
    __shared__ float s_a[2*128*20];
    __shared__ float s_b[2*16*68];

    const int row0 = blockIdx.y * 128, col0 = blockIdx.x * 64;
    const float* Ap = g_att;
    const float* Bp = Wout + col0;

    GEMM_MAIN(Ap, OUTD, Bp, IND)

#pragma unroll
    for (int rt = 0; rt < 2; rt++)
#pragma unroll
        for (int ct = 0; ct < 4; ct++)
#pragma unroll
            for (int hh = 0; hh < 2; hh++) {
                int r   = row0 + wr*32 + rt*16 + lq + 8*hh;
                int col = wc*32 + ct*8 + 2*lr;
                float2 w;
                w.x = acc[rt][ct][2*hh+0] + bout[col0 + col];
                w.y = acc[rt][ct][2*hh+1] + bout[col0 + col+1];
                *(float2*)(out + (size_t)r * IND + col0 + col) = w;
            }
}

// ============================================================
// Kernel 2: attention. BM=64 q-rows x (b,h), 4 warps, 3 blocks/SM.
// Rel B-fragments read directly from gmem (L2-resident table).
// ============================================================
#define LDT 72
#define LDP 68
#define LPS 81
#define ATTN_SMEM ((2*64*LDT + 4*16*LDP + 4*16*LPS) * (int)sizeof(float))  // 75,008 B

__global__ __launch_bounds__(128, 3) void attn_mma(const float* __restrict__ rel_emb)
{
    extern __shared__ float sm[];
    float* s_k   = sm;                        // [64][LDT]  (Q staging first)
    float* s_vt  = sm + 64*LDT;               // [64][LDT]
    float* s_p   = sm + 2*64*LDT;             // per-warp [16][LDP]
    float* s_pos = s_p + 4*16*LDP;            // per-warp [16][LPS]

    const int tid = threadIdx.x, lane = tid & 31, warp = tid >> 5;
    const int lq = lane >> 2, lr = lane & 3;
    const int n0 = blockIdx.x * 64;
    const int bh = blockIdx.y;
    const size_t base = (size_t)bh * Tn * HD;
    float* wp  = s_p  + warp*16*LDP;
    float* wps = s_pos + warp*16*LPS;

    // ---- stage Q, move A-fragments to registers ----
    for (int e = tid; e < 64*16; e += 128) {
        int i = e >> 4, d4 = (e & 15) << 2;
        *(float4*)(s_k + i*LDT + d4) =
            *(const float4*)(g_q + base + (size_t)(n0 + i)*HD + d4);
    }
    __syncthreads();
    unsigned qa[8][4];
#pragma unroll
    for (int ks = 0; ks < 8; ks++) {
        int r = warp*16 + lq, k = ks*8 + lr;
        qa[ks][0] = __float_as_uint(s_k[ r   *LDT + k]);
        qa[ks][1] = __float_as_uint(s_k[(r+8)*LDT + k]);
        qa[ks][2] = __float_as_uint(s_k[ r   *LDT + k+4]);
        qa[ks][3] = __float_as_uint(s_k[(r+8)*LDT + k+4]);
    }
    __syncthreads();

    float o[8][4];
#pragma unroll
    for (int i = 0; i < 8; i++)
#pragma unroll
        for (int j = 0; j < 4; j++) o[i][j] = 0.f;
    float mi0 = -1e30f, mi1 = -1e30f, li0 = 0.f, li1 = 0.f;

    for (int m0 = 0; m0 < Tn; m0 += 64) {
        // ---- load K, V^T ----
        for (int e = tid; e < 64*16; e += 128) {
            int i = e >> 4, d4 = (e & 15) << 2;
            float4 kv = *(const float4*)(g_k + base + (size_t)(m0 + i)*HD + d4);
            float4 vv = *(const float4*)(g_v + base + (size_t)(m0 + i)*HD + d4);
            *(float4*)(s_k + i*LDT + d4) = kv;
            s_vt[(d4+0)*LDT + i] = vv.x; s_vt[(d4+1)*LDT + i] = vv.y;
            s_vt[(d4+2)*LDT + i] = vv.z; s_vt[(d4+3)*LDT + i] = vv.w;
        }
        __syncthreads();

        // ---- S = Q K^T ----
        float sc[8][4];
#pragma unroll
        for (int i = 0; i < 8; i++)
#pragma unroll
            for (int j = 0; j < 4; j++) sc[i][j] = 0.f;
#pragma unroll
        for (int ks = 0; ks < 8; ks++)
#pragma unroll
            for (int ct = 0; ct < 8; ct++) {
                int n = ct*8 + lq, k = ks*8 + lr;
                unsigned b0 = __float_as_uint(s_k[n*LDT + k]);
                unsigned b1 = __float_as_uint(s_k[n*LDT + k+4]);
                mma8(sc[ct], qa[ks][0],qa[ks][1],qa[ks][2],qa[ks][3], b0, b1);
            }

        // ---- Pos = Q Rel^T, B-frags straight from gmem (L2) ----
        const int delta0 = n0 - m0;
#pragma unroll
        for (int ct = 0; ct < 10; ct++) {
            int dd = delta0 + warp*16 + ct*8 + lq - 63;
            dd = dd < -MAXPOS ? -MAXPOS : (dd > MAXPOS ? MAXPOS : dd);
            const float* rp = rel_emb + (size_t)(dd + MAXPOS)*HD;
            float bb[16];
#pragma unroll
            for (int ks = 0; ks < 8; ks++) {
                bb[2*ks+0] = __ldg(rp + ks*8 + lr);
                bb[2*ks+1] = __ldg(rp + ks*8 + lr + 4);
            }
            float pp[4] = {0.f, 0.f, 0.f, 0.f};
#pragma unroll
            for (int ks = 0; ks < 8; ks++)
                mma8(pp, qa[ks][0],qa[ks][1],qa[ks][2],qa[ks][3],
                     __float_as_uint(bb[2*ks]), __float_as_uint(bb[2*ks+1]));
            int c = ct*8 + 2*lr;
            wps[ lq   *LPS + c  ] = pp[0];
            wps[ lq   *LPS + c+1] = pp[1];
            wps[(lq+8)*LPS + c  ] = pp[2];
            wps[(lq+8)*LPS + c+1] = pp[3];
        }
        __syncwarp();

        // ---- add pos (diagonal gather), scale, online softmax ----
        float rmax0 = -1e30f, rmax1 = -1e30f;
#pragma unroll
        for (int ct = 0; ct < 8; ct++)
#pragma unroll
            for (int c = 0; c < 2; c++) {
                int m  = ct*8 + 2*lr + c;
                int u0 = lq - m + 63;
                float v0 = (sc[ct][c]   + wps[ lq   *LPS + u0    ]) * 0.125f;
                float v1 = (sc[ct][2+c] + wps[(lq+8)*LPS + u0 + 8]) * 0.125f;
                sc[ct][c] = v0; sc[ct][2+c] = v1;
                rmax0 = fmaxf(rmax0, v0); rmax1 = fmaxf(rmax1, v1);
            }
        rmax0 = fmaxf(rmax0, __shfl_xor_sync(~0u, rmax0, 1));
        rmax0 = fmaxf(rmax0, __shfl_xor_sync(~0u, rmax0, 2));
        rmax1 = fmaxf(rmax1, __shfl_xor_sync(~0u, rmax1, 1));
        rmax1 = fmaxf(rmax1, __shfl_xor_sync(~0u, rmax1, 2));

        float nm0 = fmaxf(mi0, rmax0), nm1 = fmaxf(mi1, rmax1);
        float cor0 = __expf(mi0 - nm0), cor1 = __expf(mi1 - nm1);
        mi0 = nm0; mi1 = nm1;

        float rs0 = 0.f, rs1 = 0.f;
#pragma unroll
        for (int ct = 0; ct < 8; ct++)
#pragma unroll
            for (int c = 0; c < 2; c++) {
                int m = ct*8 + 2*lr + c;
                float p0 = __expf(sc[ct][c]   - nm0); rs0 += p0;
                float p1 = __expf(sc[ct][2+c] - nm1); rs1 += p1;
                wp[ lq   *LDP + m] = p0;
                wp[(lq+8)*LDP + m] = p1;
            }
        rs0 += __shfl_xor_sync(~0u, rs0, 1); rs0 += __shfl_xor_sync(~0u, rs0, 2);
        rs1 += __shfl_xor_sync(~0u, rs1, 1); rs1 += __shfl_xor_sync(~0u, rs1, 2);
        li0 = li0*cor0 + rs0; li1 = li1*cor1 + rs1;
#pragma unroll
        for (int ct = 0; ct < 8; ct++) {
            o[ct][0] *= cor0; o[ct][1] *= cor0;
            o[ct][2] *= cor1; o[ct][3] *= cor1;
        }
        __syncwarp();

        // ---- O += P V ----
#pragma unroll
        for (int ks = 0; ks < 8; ks++) {
            int k = ks*8 + lr;
            unsigned a0 = __float_as_uint(wp[ lq   *LDP + k]);
            unsigned a1 = __float_as_uint(wp[(lq+8)*LDP + k]);
            unsigned a2 = __float_as_uint(wp[ lq   *LDP + k+4]);
            unsigned a3 = __float_as_uint(wp[(lq+8)*LDP + k+4]);
#pragma unroll
            for (int ct = 0; ct < 8; ct++) {
                int d = ct*8 + lq;
                unsigned b0 = __float_as_uint(s_vt[d*LDT + k]);
                unsigned b1 = __float_as_uint(s_vt[d*LDT + k+4]);
                mma8(o[ct], a0, a1, a2, a3, b0, b1);
            }
        }
        __syncthreads();
    }

    // ---- normalize, write [b, t, h*64+d] ----
    const float inv0 = 1.f / li0, inv1 = 1.f / li1;
    const int b_ = bh >> 3, h_ = bh & 7;
#pragma unroll
    for (int ct = 0; ct < 8; ct++) {
        int col = h_*HD + ct*8 + 2*lr;
        int r0  = n0 + warp*16 + lq;
        float2 w0; w0.x = o[ct][0]*inv0; w0.y = o[ct][1]*inv0;
        *(float2*)(g_att + ((size_t)(b_*Tn + r0    )*OUTD + col)) = w0;
        float2 w1; w1.x = o[ct][2]*inv1; w1.y = o[ct][3]*inv1;
        *(float2*)(g_att + ((size_t)(b_*Tn + r0 + 8)*OUTD + col)) = w1;
    }
}

// ============================================================
extern "C" void kernel_launch(void* const* d_in, const int* in_sizes, int n_in,
                              void* d_out, int out_size)
{
    const float* x    = (const float*)d_in[0];
    const float* Wq   = (const float*)d_in[1];
    const float* bq   = (const float*)d_in[2];
    const float* Wkv  = (const float*)d_in[3];
    const float* bkv  = (const float*)d_in[4];
    const float* Wout = (const float*)d_in[5];
    const float* bout = (const float*)d_in[6];
    const float* rel  = (const float*)d_in[7];
    float* out = (float*)d_out;

    cudaFuncSetAttribute(attn_mma,
                         cudaFuncAttributeMaxDynamicSharedMemorySize, ATTN_SMEM);

    qkv_mma<<<dim3(24, 64), 256>>>(x, Wq, bq, Wkv, bkv);
    attn_mma<<<dim3(16, 64), 128, ATTN_SMEM>>>(rel);
    out_mma<<<dim3(8, 64), 256>>>(Wout, bout, out);
}

// round 5
// speedup vs baseline: 2.1580x; 2.1580x over previous
#include <cuda_runtime.h>
#include <cuda_fp16.h>

#define Bn 8
#define Tn 1024
#define IND 512
#define NH 8
#define HD 64
#define OUTD 512
#define MAXPOS 512

// -------- scratch (allocations forbidden; device globals) --------
__device__ __half g_xh [(size_t)Bn*Tn*IND];
__device__ __half g_wqh[(size_t)OUTD*IND];        // [n][k]
__device__ __half g_wkvh[(size_t)2*OUTD*IND];     // [n][k]
__device__ __half g_wouth[(size_t)IND*OUTD];      // [n][k]
__device__ __half g_relh[(size_t)(2*MAXPOS+1)*HD];
__device__ __half g_qh[(size_t)Bn*NH*Tn*HD];
__device__ __half g_kh[(size_t)Bn*NH*Tn*HD];
__device__ __half g_vh[(size_t)Bn*NH*Tn*HD];
__device__ __half g_atth[(size_t)Bn*Tn*OUTD];

// -------- helpers --------
__device__ __forceinline__ void mma16(float* c,
    unsigned a0, unsigned a1, unsigned a2, unsigned a3,
    unsigned b0, unsigned b1)
{
    asm volatile(
      "mma.sync.aligned.m16n8k16.row.col.f32.f16.f16.f32 "
      "{%0,%1,%2,%3},{%4,%5,%6,%7},{%8,%9},{%0,%1,%2,%3};"
      : "+f"(c[0]), "+f"(c[1]), "+f"(c[2]), "+f"(c[3])
      : "r"(a0), "r"(a1), "r"(a2), "r"(a3), "r"(b0), "r"(b1));
}
__device__ __forceinline__ void cpa8(unsigned dst, const void* src) {
    asm volatile("cp.async.ca.shared.global [%0], [%1], 8;" :: "r"(dst), "l"(src));
}
__device__ __forceinline__ void cpa_commit() { asm volatile("cp.async.commit_group;"); }
__device__ __forceinline__ unsigned ldu(const __half* p) { return *(const unsigned*)p; }

// ============================================================
// conversion kernels
// ============================================================
__global__ void conv_f2h(const float* __restrict__ src, __half* __restrict__ dst, int n4)
{
    int i = blockIdx.x * blockDim.x + threadIdx.x;
    if (i >= n4) return;
    float4 v = *(const float4*)(src + 4*i);
    *(__half2*)(dst + 4*i)     = __floats2half2_rn(v.x, v.y);
    *(__half2*)(dst + 4*i + 2) = __floats2half2_rn(v.z, v.w);
}
// W [K][N] fp32 -> dst [N][K] half
__global__ void conv_wT(const float* __restrict__ src, __half* __restrict__ dst,
                        int K, int N)
{
    int i = blockIdx.x * blockDim.x + threadIdx.x;
    if (i >= (K*N)/4) return;
    int k = (4*i) / N, n0 = (4*i) % N;
    float4 v = *(const float4*)(src + 4*i);
    dst[(size_t)(n0+0)*K + k] = __float2half_rn(v.x);
    dst[(size_t)(n0+1)*K + k] = __float2half_rn(v.y);
    dst[(size_t)(n0+2)*K + k] = __float2half_rn(v.z);
    dst[(size_t)(n0+3)*K + k] = __float2half_rn(v.w);
}

// ============================================================
// fp16 GEMM body: BM=128, BN=64, BK=32, 256 thr, double-buffered
// cp.async. A [row][k] half, B [n][k] half (k-stride 512). 16 k-iters.
// ============================================================
#define LDS_S 40
#define HGEMM(APTR, LDA, BPTR)                                                  \
    const int tid = threadIdx.x, lane = tid & 31, warp = tid >> 5;              \
    const int wr = warp >> 1, wc = warp & 1;                                    \
    const int lq = lane >> 2, lr = lane & 3;                                    \
    unsigned sa_u = (unsigned)__cvta_generic_to_shared(s_a);                    \
    unsigned sb_u = (unsigned)__cvta_generic_to_shared(s_b);                    \
    float acc[2][4][4];                                                         \
    _Pragma("unroll") for (int i = 0; i < 2; i++)                               \
    _Pragma("unroll") for (int j = 0; j < 4; j++)                               \
    _Pragma("unroll") for (int e = 0; e < 4; e++) acc[i][j][e] = 0.f;           \
    {                                                                           \
        _Pragma("unroll")                                                       \
        for (int j = 0; j < 4; j++) {                                           \
            int c = tid + j*256, row = c >> 3, c4 = (c & 7) << 2;               \
            cpa8(sa_u + row*(LDS_S*2) + c4*2,                                   \
                 (APTR) + (size_t)(row0 + row)*(LDA) + c4);                     \
        }                                                                       \
        _Pragma("unroll")                                                       \
        for (int j = 0; j < 2; j++) {                                           \
            int c = tid + j*256, n = c >> 3, c4 = (c & 7) << 2;                 \
            cpa8(sb_u + n*(LDS_S*2) + c4*2,                                     \
                 (BPTR) + (size_t)n*IND + c4);                                  \
        }                                                                       \
        cpa_commit();                                                           \
    }                                                                           \
    for (int it = 0; it < 16; it++) {                                           \
        const int buf = it & 1;                                                 \
        if (it < 15) {                                                          \
            const int kn = (it+1) << 5;                                         \
            const unsigned ao = (buf^1) * (128*LDS_S*2);                        \
            const unsigned bo = (buf^1) * (64*LDS_S*2);                         \
            _Pragma("unroll")                                                   \
            for (int j = 0; j < 4; j++) {                                       \
                int c = tid + j*256, row = c >> 3, c4 = (c & 7) << 2;           \
                cpa8(sa_u + ao + row*(LDS_S*2) + c4*2,                          \
                     (APTR) + (size_t)(row0 + row)*(LDA) + kn + c4);            \
            }                                                                   \
            _Pragma("unroll")                                                   \
            for (int j = 0; j < 2; j++) {                                       \
                int c = tid + j*256, n = c >> 3, c4 = (c & 7) << 2;             \
                cpa8(sb_u + bo + n*(LDS_S*2) + c4*2,                            \
                     (BPTR) + (size_t)n*IND + kn + c4);                         \
            }                                                                   \
            cpa_commit();                                                       \
            asm volatile("cp.async.wait_group 1;");                             \
        } else {                                                                \
            asm volatile("cp.async.wait_group 0;");                             \
        }                                                                       \
        __syncthreads();                                                        \
        const __half* pa = s_a + buf*(128*LDS_S);                               \
        const __half* pb = s_b + buf*(64*LDS_S);                                \
        _Pragma("unroll")                                                       \
        for (int ks = 0; ks < 2; ks++) {                                        \
            const int kb = ks*16 + 2*lr;                                        \
            unsigned a[2][4], b[4][2];                                          \
            _Pragma("unroll")                                                   \
            for (int rt = 0; rt < 2; rt++) {                                    \
                int r = wr*32 + rt*16 + lq;                                     \
                a[rt][0] = ldu(pa +  r   *LDS_S + kb);                          \
                a[rt][1] = ldu(pa + (r+8)*LDS_S + kb);                          \
                a[rt][2] = ldu(pa +  r   *LDS_S + kb + 8);                      \
                a[rt][3] = ldu(pa + (r+8)*LDS_S + kb + 8);                      \
            }                                                                   \
            _Pragma("unroll")                                                   \
            for (int ct = 0; ct < 4; ct++) {                                    \
                int n = wc*32 + ct*8 + lq;                                      \
                b[ct][0] = ldu(pb + n*LDS_S + kb);                              \
                b[ct][1] = ldu(pb + n*LDS_S + kb + 8);                          \
            }                                                                   \
            _Pragma("unroll")                                                   \
            for (int rt = 0; rt < 2; rt++)                                      \
            _Pragma("unroll")                                                   \
            for (int ct = 0; ct < 4; ct++)                                      \
                mma16(acc[rt][ct], a[rt][0],a[rt][1],a[rt][2],a[rt][3],         \
                      b[ct][0],b[ct][1]);                                       \
        }                                                                       \
        __syncthreads();                                                        \
    }

// ============================================================
// Kernel 1: QKV projection (fp16)
// ============================================================
__global__ __launch_bounds__(256) void qkv_mma(
    const float* __restrict__ bq, const float* __restrict__ bkv)
{
    __shared__ __half s_a[2*128*LDS_S];
    __shared__ __half s_b[2*64*LDS_S];

    const int row0 = blockIdx.y * 128, col0 = blockIdx.x * 64;
    const __half* Bp; const float* bias;
    if (col0 < OUTD) { Bp = g_wqh  + (size_t)col0*IND;         bias = bq  + col0; }
    else             { Bp = g_wkvh + (size_t)(col0-OUTD)*IND;  bias = bkv + (col0-OUTD); }

    HGEMM(g_xh, IND, Bp)

    const int seg = col0 >> 9;
    const int h   = (col0 & 511) >> 6;
    __half* dst = (seg == 0) ? g_qh : (seg == 1) ? g_kh : g_vh;

#pragma unroll
    for (int rt = 0; rt < 2; rt++)
#pragma unroll
        for (int ct = 0; ct < 4; ct++)
#pragma unroll
            for (int hh = 0; hh < 2; hh++) {
                int r  = row0 + wr*32 + rt*16 + lq + 8*hh;
                int bb = r >> 10, tt = r & 1023;
                int col = wc*32 + ct*8 + 2*lr;
                __half2 w = __floats2half2_rn(acc[rt][ct][2*hh+0] + bias[col],
                                              acc[rt][ct][2*hh+1] + bias[col+1]);
                *(__half2*)(dst + ((size_t)(bb*NH + h)*Tn + tt)*HD + col) = w;
            }
}

// ============================================================
// Kernel 3: output projection (fp16 -> fp32 out)
// ============================================================
__global__ __launch_bounds__(256) void out_mma(
    const float* __restrict__ bout, float* __restrict__ out)
{
    __shared__ __half s_a[2*128*LDS_S];
    __shared__ __half s_b[2*64*LDS_S];

    const int row0 = blockIdx.y * 128, col0 = blockIdx.x * 64;
    const __half* Bp = g_wouth + (size_t)col0*OUTD;

    HGEMM(g_atth, OUTD, Bp)

#pragma unroll
    for (int rt = 0; rt < 2; rt++)
#pragma unroll
        for (int ct = 0; ct < 4; ct++)
#pragma unroll
            for (int hh = 0; hh < 2; hh++) {
                int r   = row0 + wr*32 + rt*16 + lq + 8*hh;
                int col = wc*32 + ct*8 + 2*lr;
                float2 w;
                w.x = acc[rt][ct][2*hh+0] + bout[col0 + col];
                w.y = acc[rt][ct][2*hh+1] + bout[col0 + col+1];
                *(float2*)(out + (size_t)r * IND + col0 + col) = w;
            }
}

// ============================================================
// Kernel 2: attention (fp16 mma, fp32 softmax). Dynamic smem.
// Block = 64 q-rows x one (b,h); 4 warps (16 rows each).
// LDH=72 halfs: fragment reads hit all 32 banks (conflict-free).
// ============================================================
#define LDH 72
#define LPS 81
#define ATTN_H ((64 + 64 + 128 + 4*16) * LDH)                 // halfs
#define ATTN_SMEM (ATTN_H*2 + 4*16*LPS*4)                     // 66,816 B

__global__ __launch_bounds__(128, 3) void attn_mma()
{
    extern __shared__ __half smh[];
    __half* s_k   = smh;                    // [64][LDH]  (Q staged first)
    __half* s_vt  = smh + 64*LDH;           // [64][LDH]  V^T [d][m]
    __half* s_rel = smh + 2*64*LDH;         // [128][LDH]
    __half* s_p   = smh + 2*64*LDH + 128*LDH;   // per-warp [16][LDH]
    float*  s_pos = (float*)(smh + ATTN_H); // per-warp [16][LPS]

    const int tid = threadIdx.x, lane = tid & 31, warp = tid >> 5;
    const int lq = lane >> 2, lr = lane & 3;
    const int n0 = blockIdx.x * 64;
    const int bh = blockIdx.y;
    const size_t base = (size_t)bh * Tn * HD;
    __half* wp  = s_p  + warp*16*LDH;
    float*  wps = s_pos + warp*16*LPS;

    // ---- stage Q tile, move A-fragments to registers ----
    for (int e = tid; e < 64*16; e += 128) {
        int m = e >> 4, c4 = (e & 15) << 2;
        *(uint2*)(s_k + m*LDH + c4) = *(const uint2*)(g_qh + base + (size_t)(n0+m)*HD + c4);
    }
    __syncthreads();
    unsigned qa[4][4];
#pragma unroll
    for (int ks = 0; ks < 4; ks++) {
        int r = warp*16 + lq, kb = ks*16 + 2*lr;
        qa[ks][0] = ldu(s_k +  r   *LDH + kb);
        qa[ks][1] = ldu(s_k + (r+8)*LDH + kb);
        qa[ks][2] = ldu(s_k +  r   *LDH + kb + 8);
        qa[ks][3] = ldu(s_k + (r+8)*LDH + kb + 8);
    }
    __syncthreads();

    float o[8][4];
#pragma unroll
    for (int i = 0; i < 8; i++)
#pragma unroll
        for (int j = 0; j < 4; j++) o[i][j] = 0.f;
    float mi0 = -1e30f, mi1 = -1e30f, li0 = 0.f, li1 = 0.f;

    for (int m0 = 0; m0 < Tn; m0 += 64) {
        // ---- stage K, V^T, rel window ----
        for (int e = tid; e < 64*16; e += 128) {
            int m = e >> 4, c4 = (e & 15) << 2;
            *(uint2*)(s_k + m*LDH + c4) = *(const uint2*)(g_kh + base + (size_t)(m0+m)*HD + c4);
        }
        for (int e = tid; e < 64*32; e += 128) {
            int m = e >> 5, dp = (e & 31) << 1;
            __half2 v = *(const __half2*)(g_vh + base + (size_t)(m0+m)*HD + dp);
            s_vt[ dp   *LDH + m] = __low2half(v);
            s_vt[(dp+1)*LDH + m] = __high2half(v);
        }
        const int delta0 = n0 - m0;
        for (int e = tid; e < 128*16; e += 128) {
            int r = e >> 4, c4 = (e & 15) << 2;
            int dd = delta0 + r - 63;
            dd = dd < -MAXPOS ? -MAXPOS : (dd > MAXPOS ? MAXPOS : dd);
            *(uint2*)(s_rel + r*LDH + c4) = *(const uint2*)(g_relh + (size_t)(dd+MAXPOS)*HD + c4);
        }
        __syncthreads();

        // ---- S = Q K^T ----
        float sc[8][4];
#pragma unroll
        for (int i = 0; i < 8; i++)
#pragma unroll
            for (int j = 0; j < 4; j++) sc[i][j] = 0.f;
#pragma unroll
        for (int ks = 0; ks < 4; ks++) {
            const int kb = ks*16 + 2*lr;
#pragma unroll
            for (int ct = 0; ct < 8; ct++) {
                int n = ct*8 + lq;
                unsigned b0 = ldu(s_k + n*LDH + kb);
                unsigned b1 = ldu(s_k + n*LDH + kb + 8);
                mma16(sc[ct], qa[ks][0],qa[ks][1],qa[ks][2],qa[ks][3], b0, b1);
            }
        }

        // ---- Pos = Q Rel^T over this warp's 80-col window ----
#pragma unroll
        for (int ct = 0; ct < 10; ct++) {
            float pp[4] = {0.f, 0.f, 0.f, 0.f};
            int n = warp*16 + ct*8 + lq;
#pragma unroll
            for (int ks = 0; ks < 4; ks++) {
                const int kb = ks*16 + 2*lr;
                unsigned b0 = ldu(s_rel + n*LDH + kb);
                unsigned b1 = ldu(s_rel + n*LDH + kb + 8);
                mma16(pp, qa[ks][0],qa[ks][1],qa[ks][2],qa[ks][3], b0, b1);
            }
            int c = ct*8 + 2*lr;
            wps[ lq   *LPS + c  ] = pp[0];
            wps[ lq   *LPS + c+1] = pp[1];
            wps[(lq+8)*LPS + c  ] = pp[2];
            wps[(lq+8)*LPS + c+1] = pp[3];
        }
        __syncwarp();

        // ---- add pos (diagonal gather), scale, online softmax ----
        float rmax0 = -1e30f, rmax1 = -1e30f;
#pragma unroll
        for (int ct = 0; ct < 8; ct++)
#pragma unroll
            for (int c = 0; c < 2; c++) {
                int m  = ct*8 + 2*lr + c;
                int u0 = lq - m + 63;
                float v0 = (sc[ct][c]   + wps[ lq   *LPS + u0    ]) * 0.125f;
                float v1 = (sc[ct][2+c] + wps[(lq+8)*LPS + u0 + 8]) * 0.125f;
                sc[ct][c] = v0; sc[ct][2+c] = v1;
                rmax0 = fmaxf(rmax0, v0); rmax1 = fmaxf(rmax1, v1);
            }
        rmax0 = fmaxf(rmax0, __shfl_xor_sync(~0u, rmax0, 1));
        rmax0 = fmaxf(rmax0, __shfl_xor_sync(~0u, rmax0, 2));
        rmax1 = fmaxf(rmax1, __shfl_xor_sync(~0u, rmax1, 1));
        rmax1 = fmaxf(rmax1, __shfl_xor_sync(~0u, rmax1, 2));

        float nm0 = fmaxf(mi0, rmax0), nm1 = fmaxf(mi1, rmax1);
        float cor0 = __expf(mi0 - nm0), cor1 = __expf(mi1 - nm1);
        mi0 = nm0; mi1 = nm1;

        float rs0 = 0.f, rs1 = 0.f;
#pragma unroll
        for (int ct = 0; ct < 8; ct++) {
            float p00 = __expf(sc[ct][0] - nm0), p01 = __expf(sc[ct][1] - nm0);
            float p10 = __expf(sc[ct][2] - nm1), p11 = __expf(sc[ct][3] - nm1);
            rs0 += p00 + p01; rs1 += p10 + p11;
            int c = ct*8 + 2*lr;
            *(__half2*)(wp +  lq   *LDH + c) = __floats2half2_rn(p00, p01);
            *(__half2*)(wp + (lq+8)*LDH + c) = __floats2half2_rn(p10, p11);
        }
        rs0 += __shfl_xor_sync(~0u, rs0, 1); rs0 += __shfl_xor_sync(~0u, rs0, 2);
        rs1 += __shfl_xor_sync(~0u, rs1, 1); rs1 += __shfl_xor_sync(~0u, rs1, 2);
        li0 = li0*cor0 + rs0; li1 = li1*cor1 + rs1;
#pragma unroll
        for (int ct = 0; ct < 8; ct++) {
            o[ct][0] *= cor0; o[ct][1] *= cor0;
            o[ct][2] *= cor1; o[ct][3] *= cor1;
        }
        __syncwarp();

        // ---- O += P V ----
#pragma unroll
        for (int ks = 0; ks < 4; ks++) {
            const int kb = ks*16 + 2*lr;
            unsigned a0 = ldu(wp +  lq   *LDH + kb);
            unsigned a1 = ldu(wp + (lq+8)*LDH + kb);
            unsigned a2 = ldu(wp +  lq   *LDH + kb + 8);
            unsigned a3 = ldu(wp + (lq+8)*LDH + kb + 8);
#pragma unroll
            for (int ct = 0; ct < 8; ct++) {
                int d = ct*8 + lq;
                unsigned b0 = ldu(s_vt + d*LDH + kb);
                unsigned b1 = ldu(s_vt + d*LDH + kb + 8);
                mma16(o[ct], a0, a1, a2, a3, b0, b1);
            }
        }
        __syncthreads();
    }

    // ---- normalize, write half to g_atth [b, t, h*64+d] ----
    const float inv0 = 1.f / li0, inv1 = 1.f / li1;
    const int b_ = bh >> 3, h_ = bh & 7;
#pragma unroll
    for (int ct = 0; ct < 8; ct++) {
        int col = h_*HD + ct*8 + 2*lr;
        int r0  = n0 + warp*16 + lq;
        *(__half2*)(g_atth + ((size_t)(b_*Tn + r0    )*OUTD + col)) =
            __floats2half2_rn(o[ct][0]*inv0, o[ct][1]*inv0);
        *(__half2*)(g_atth + ((size_t)(b_*Tn + r0 + 8)*OUTD + col)) =
            __floats2half2_rn(o[ct][2]*inv1, o[ct][3]*inv1);
    }
}

// ============================================================
extern "C" void kernel_launch(void* const* d_in, const int* in_sizes, int n_in,
                              void* d_out, int out_size)
{
    const float* x    = (const float*)d_in[0];
    const float* Wq   = (const float*)d_in[1];
    const float* bq   = (const float*)d_in[2];
    const float* Wkv  = (const float*)d_in[3];
    const float* bkv  = (const float*)d_in[4];
    const float* Wout = (const float*)d_in[5];
    const float* bout = (const float*)d_in[6];
    const float* rel  = (const float*)d_in[7];
    float* out = (float*)d_out;

    __half* xh;   cudaGetSymbolAddress((void**)&xh,   g_xh);
    __half* wqh;  cudaGetSymbolAddress((void**)&wqh,  g_wqh);
    __half* wkvh; cudaGetSymbolAddress((void**)&wkvh, g_wkvh);
    __half* wouth;cudaGetSymbolAddress((void**)&wouth,g_wouth);
    __half* relh; cudaGetSymbolAddress((void**)&relh, g_relh);

    cudaFuncSetAttribute(attn_mma,
                         cudaFuncAttributeMaxDynamicSharedMemorySize, ATTN_SMEM);

    conv_f2h<<<(Bn*Tn*IND/4 + 255)/256, 256>>>(x, xh, Bn*Tn*IND/4);
    conv_f2h<<<((2*MAXPOS+1)*HD/4 + 255)/256, 256>>>(rel, relh, (2*MAXPOS+1)*HD/4);
    conv_wT<<<(IND*OUTD/4 + 255)/256, 256>>>(Wq,   wqh,   IND, OUTD);
    conv_wT<<<(IND*2*OUTD/4 + 255)/256, 256>>>(Wkv, wkvh,  IND, 2*OUTD);
    conv_wT<<<(OUTD*IND/4 + 255)/256, 256>>>(Wout, wouth, OUTD, IND);

    qkv_mma<<<dim3(24, 64), 256>>>(bq, bkv);
    attn_mma<<<dim3(16, 64), 128, ATTN_SMEM>>>();
    out_mma<<<dim3(8, 64), 256>>>(bout, out);
}